// round 9
// baseline (speedup 1.0000x reference)
#include <cuda_runtime.h>
#include <math.h>

#define BB 8
#define XX 128
#define YY 128
#define WW 24
#define DD 4
#define YHH 65
#define NPIX (BB*XX*YY)        // 131072
#define NROWS (BB*XX)          // 1024
#define NFREQ (XX*YHH)         // 8320
#define IOSZ (WW*WW)           // 576

// ---------------- device scratch (static: no allocations allowed) ------------
__device__ float  d_h[(size_t)NPIX*WW];             // (B,X,Y,W)      12.6 MB
__device__ float2 d_hf[(size_t)NROWS*YHH*WW];       // (B,X,YH,W)     12.8 MB
__device__ float2 d_spec[(size_t)NROWS*YHH*WW];     // (B,X,YH,W)     12.8 MB
__device__ float2 d_wt[(size_t)DD*NFREQ*IOSZ];      // (D,f,i,o)     153.4 MB
__device__ float2 d_tw[128];                        // exp(-i*pi*k/64)

__device__ __forceinline__ float4 cmul4(float4 v, float2 w) {
    return make_float4(v.x*w.x - v.y*w.y, v.x*w.y + v.y*w.x,
                       v.z*w.x - v.w*w.y, v.z*w.y + v.w*w.x);
}
__device__ __forceinline__ float4 add4(float4 a, float4 b) {
    return make_float4(a.x+b.x, a.y+b.y, a.z+b.z, a.w+b.w);
}
__device__ __forceinline__ float4 sub4(float4 a, float4 b) {
    return make_float4(a.x-b.x, a.y-b.y, a.z-b.z, a.w-b.w);
}
// fwd: multiply both packed complex by -j ; inv: by +j
template<bool INV>
__device__ __forceinline__ float4 mulj4(float4 v) {
    return INV ? make_float4(-v.y, v.x, -v.w, v.z)
               : make_float4( v.y,-v.x,  v.w,-v.z);
}

// ---------------- twiddle table ----------------------------------------------
__global__ void k_twiddle() {
    int k = threadIdx.x;
    double s, c;
    sincospi(-(double)k / 64.0, &s, &c);
    d_tw[k] = make_float2((float)c, (float)s);
}

// ---------------- weight transpose: (d, io, f) -> (d, f, io) ------------------
__global__ void k_transpose(const float2* __restrict__ src) {
    __shared__ float2 tile[32][33];
    int dd  = blockIdx.z;
    int f0  = blockIdx.x * 32;
    int io0 = blockIdx.y * 32;
    const float2* s = src + (size_t)dd * IOSZ * NFREQ;
    #pragma unroll
    for (int j = 0; j < 4; j++) {
        int io = io0 + threadIdx.y + j*8;
        int f  = f0 + threadIdx.x;
        tile[threadIdx.y + j*8][threadIdx.x] = s[(size_t)io * NFREQ + f];
    }
    __syncthreads();
    float2* dst = d_wt + (size_t)dd * NFREQ * IOSZ;
    #pragma unroll
    for (int j = 0; j < 4; j++) {
        int f  = f0 + threadIdx.y + j*8;
        int io = io0 + threadIdx.x;
        dst[(size_t)f * IOSZ + io] = tile[threadIdx.x][threadIdx.y + j*8];
    }
}

// ---------------- 128-point Stockham FFT, radix 4*4*8, fused I/O --------------
// LP float4 lanes per point (2 complex lines each). Layout buf[point*LP + lp].
// Stage 1 reads via ld(point, lp); stage 3 writes via st(point, lp, val).
// s1: ld -> b0; sync; s2: b0 -> b1; sync; s3: b1 -> st. NO trailing sync.
// The buffer ld reads from may alias b1 (stage 2 clobbers it only after the
// stage-1 barrier); st may alias b0 (consumed by stage 2 before the barrier).
template<int LP, bool INV, int NT, class LD, class ST>
__device__ __forceinline__ void fft128_io(float4* b0, float4* b1, int tid,
                                          const float2* __restrict__ tw,
                                          LD ld, ST st) {
    // -------- stage 1: radix-4, s=1 --------
    #pragma unroll 2
    for (int idx = tid; idx < 32*LP; idx += NT) {
        int lp = idx % LP;
        int p  = idx / LP;                     // 0..31
        float4 a = ld(p,      lp);
        float4 b = ld(p + 32, lp);
        float4 c = ld(p + 64, lp);
        float4 d = ld(p + 96, lp);
        float2 w1 = tw[p], w2 = tw[2*p], w3 = tw[3*p];
        if (INV) { w1.y = -w1.y; w2.y = -w2.y; w3.y = -w3.y; }
        float4 apc = add4(a, c), amc = sub4(a, c);
        float4 bpd = add4(b, d), bmd = sub4(b, d);
        float4 jb  = mulj4<INV>(bmd);
        int ob = 4*p;
        b0[(ob    )*LP + lp] = add4(apc, bpd);
        b0[(ob + 1)*LP + lp] = cmul4(add4(amc, jb), w1);
        b0[(ob + 2)*LP + lp] = cmul4(sub4(apc, bpd), w2);
        b0[(ob + 3)*LP + lp] = cmul4(sub4(amc, jb), w3);
    }
    __syncthreads();
    // -------- stage 2: radix-4, s=4 --------
    #pragma unroll 2
    for (int idx = tid; idx < 32*LP; idx += NT) {
        int lp = idx % LP;
        int bf = idx / LP;
        int q = bf & 3, p = bf >> 2;           // p 0..7
        int base = q + 4*p;
        float4 a = b0[ base      *LP + lp];
        float4 b = b0[(base+32 )*LP + lp];
        float4 c = b0[(base+64 )*LP + lp];
        float4 d = b0[(base+96 )*LP + lp];
        float2 w1 = tw[4*p], w2 = tw[8*p], w3 = tw[12*p];
        if (INV) { w1.y = -w1.y; w2.y = -w2.y; w3.y = -w3.y; }
        float4 apc = add4(a, c), amc = sub4(a, c);
        float4 bpd = add4(b, d), bmd = sub4(b, d);
        float4 jb  = mulj4<INV>(bmd);
        int ob = q + 16*p;
        b1[(ob     )*LP + lp] = add4(apc, bpd);
        b1[(ob + 4 )*LP + lp] = cmul4(add4(amc, jb), w1);
        b1[(ob + 8 )*LP + lp] = cmul4(sub4(apc, bpd), w2);
        b1[(ob + 12)*LP + lp] = cmul4(sub4(amc, jb), w3);
    }
    __syncthreads();
    // -------- stage 3: radix-8, s=16, p=0 (no table twiddles) --------
    const float C = 0.70710678118654752f;
    #pragma unroll 2
    for (int idx = tid; idx < 16*LP; idx += NT) {
        int lp = idx % LP;
        int q  = idx / LP;                     // 0..15
        float4 x0 = b1[(q       )*LP + lp];
        float4 x1 = b1[(q + 16 )*LP + lp];
        float4 x2 = b1[(q + 32 )*LP + lp];
        float4 x3 = b1[(q + 48 )*LP + lp];
        float4 x4 = b1[(q + 64 )*LP + lp];
        float4 x5 = b1[(q + 80 )*LP + lp];
        float4 x6 = b1[(q + 96 )*LP + lp];
        float4 x7 = b1[(q + 112)*LP + lp];
        float4 t0 = add4(x0, x4), t1 = sub4(x0, x4);
        float4 t2 = add4(x2, x6), t3 = sub4(x2, x6);
        float4 jt3 = mulj4<INV>(t3);
        float4 e0 = add4(t0, t2), e2 = sub4(t0, t2);
        float4 e1 = add4(t1, jt3), e3 = sub4(t1, jt3);
        float4 u0 = add4(x1, x5), u1 = sub4(x1, x5);
        float4 u2 = add4(x3, x7), u3 = sub4(x3, x7);
        float4 ju3 = mulj4<INV>(u3);
        float4 o0 = add4(u0, u2), o2 = sub4(u0, u2);
        float4 o1 = add4(u1, ju3), o3 = sub4(u1, ju3);
        float2 w81 = INV ? make_float2( C,  C) : make_float2( C, -C);
        float2 w83 = INV ? make_float2(-C,  C) : make_float2(-C, -C);
        float4 o1w = cmul4(o1, w81);
        float4 o2w = mulj4<INV>(o2);
        float4 o3w = cmul4(o3, w83);
        st(q      , lp, add4(e0, o0));
        st(q + 16 , lp, add4(e1, o1w));
        st(q + 32 , lp, add4(e2, o2w));
        st(q + 48 , lp, add4(e3, o3w));
        st(q + 64 , lp, sub4(e0, o0));
        st(q + 80 , lp, sub4(e1, o1w));
        st(q + 96 , lp, sub4(e2, o2w));
        st(q + 112, lp, sub4(e3, o3w));
    }
}

// ---------------- in mapping ---------------------------------------------------
__global__ void k_inmap(const float* __restrict__ x,
                        const float* __restrict__ iw,
                        const float* __restrict__ ib) {
    int p = blockIdx.x * blockDim.x + threadIdx.x;
    if (p >= NPIX) return;
    float a = x[2*p], b = x[2*p + 1];
    float* out = d_h + (size_t)p * WW;
    #pragma unroll
    for (int w = 0; w < WW; w++)
        out[w] = a*iw[w] + b*iw[WW + w] + ib[w];
}

// ---------------- rfft along y per (b,x) row (runs once; fully fused I/O) -----
__global__ void k_rfft_y() {
    extern __shared__ float4 sm4[];
    float4* bufA = sm4;                 // 128*12
    float4* bufB = sm4 + 128*12;
    __shared__ float2 tw[128];
    int tid = threadIdx.x;
    if (tid < 128) tw[tid] = d_tw[tid];
    __syncthreads();
    int row = blockIdx.x;
    const float* hsrc = d_h + (size_t)row * YY * WW;
    float4* hfo = (float4*)(d_hf + (size_t)row * YHH * WW);
    auto ld = [&](int p, int lp) {
        return make_float4(hsrc[p*24 + 2*lp], 0.0f, hsrc[p*24 + 2*lp + 1], 0.0f);
    };
    auto st = [&](int p, int lp, float4 v) {
        if (p < YHH) hfo[p*12 + lp] = v;
    };
    fft128_io<12,false,512>(bufA, bufB, tid, tw, ld, st);
}

// ---------------- fused fft-x + spectral matmul + ifft-x ----------------------
// block = (yh, batch-pair of 2). 48 lines = 24 float4 lanes. smem 96KB, 2 CTA/SM
// Hybrid I/O: streaming preload (MLP=6) for the forward input; fused smem store
// for the forward output; fused global scatter for the inverse output.
__global__ __launch_bounds__(512) void k_spectral(int layer) {
    extern __shared__ float4 sm4[];
    float4* bufA = sm4;                 // 128*24
    float4* bufB = sm4 + 128*24;
    __shared__ float2 tw[128];
    int tid = threadIdx.x;
    if (tid < 128) tw[tid] = d_tw[tid];
    int yh  = blockIdx.x >> 2;
    int b0i = (blockIdx.x & 3) * 2;

    // streaming preload hf -> bufA (6 independent float4 LDGs per thread)
    {
        const float4* hf4 = (const float4*)d_hf;
        #pragma unroll
        for (int k = 0; k < 6; k++) {
            int idx = tid + k*512;
            int x = idx / 24, l = idx % 24;
            int b = b0i + l/12, ip = l % 12;
            bufA[idx] = hf4[(((size_t)b*XX + x)*YHH + yh)*12 + ip];
        }
    }
    __syncthreads();

    // forward x-FFT: bufA -> (B,A ping-pong) -> F in bufB
    auto ldf = [&](int p, int lp) { return bufA[p*24 + lp]; };
    auto stf = [&](int p, int lp, float4 v) { bufB[p*24 + lp] = v; };
    fft128_io<24,false,512>(bufB, bufA, tid, tw, ldf, stf);
    __syncthreads();

    // yf[b][o] = sum_i hf[b][i] * w[i][o]; F=bufB -> G=bufA
    const float2* wt = d_wt + (size_t)layer * NFREQ * IOSZ;
    const float2* F = (const float2*)bufB;
    float4* G4 = bufA;
    #pragma unroll 2
    for (int j = tid; j < 128*12; j += 512) {
        int x = j / 12, op = j % 12, o = op * 2;
        const float4* wp4 = (const float4*)(wt + ((size_t)x*YHH + yh)*IOSZ + o);
        const float2* hp  = F + x*48;
        float2 a00 = {0,0}, a01 = {0,0}, a10 = {0,0}, a11 = {0,0};
        #pragma unroll
        for (int i = 0; i < WW; i++) {
            float4 w4 = __ldg(wp4 + i*12);           // w[i][o], w[i][o+1]
            float2 w0 = make_float2(w4.x, w4.y);
            float2 w1 = make_float2(w4.z, w4.w);
            float2 h0 = hp[i], h1 = hp[24+i];
            a00.x += h0.x*w0.x - h0.y*w0.y;  a00.y += h0.x*w0.y + h0.y*w0.x;
            a01.x += h0.x*w1.x - h0.y*w1.y;  a01.y += h0.x*w1.y + h0.y*w1.x;
            a10.x += h1.x*w0.x - h1.y*w0.y;  a10.y += h1.x*w0.y + h1.y*w0.x;
            a11.x += h1.x*w1.x - h1.y*w1.y;  a11.y += h1.x*w1.y + h1.y*w1.x;
        }
        G4[(x*48 + o) >> 1]      = make_float4(a00.x, a00.y, a01.x, a01.y);
        G4[(x*48 + 24 + o) >> 1] = make_float4(a10.x, a10.y, a11.x, a11.y);
    }
    __syncthreads();

    // inverse x-FFT: G=bufA -> (B,A ping-pong) -> scatter to d_spec
    float4* sp4 = (float4*)d_spec;
    auto ldi = [&](int p, int lp) { return bufA[p*24 + lp]; };
    auto sti = [&](int p, int lp, float4 v) {
        int b = b0i + lp/12, ip = lp % 12;
        sp4[(((size_t)b*XX + p)*YHH + yh)*12 + ip] = v;
    };
    fft128_io<24,true,512>(bufB, bufA, tid, tw, ldi, sti);
}

// ---------------- fused irfft-y + 1x1 conv + relu (+ out-map) (+ next rfft-y) -
// 2 rows per block, 256 threads. Channel-pair packing: 12 complex lines per row.
// Hybrid I/O: streaming pack loop (MLP=12) feeds the inverse FFT from smem.
// irfft semantics: DC/Nyquist imaginary parts are ignored -> dropped on pack.
__global__ __launch_bounds__(256) void k_update(int layer, int t, int Trt, int flags,
                         const float* __restrict__ conv_w,
                         const float* __restrict__ conv_b,
                         const float* __restrict__ out_w,
                         const float* __restrict__ out_b,
                         float* __restrict__ outp) {
    extern __shared__ float4 sm4[];
    float4* A4  = sm4;                        // 128*12 (2 rows x 6 lanes)
    float4* B4  = sm4 + 128*12;
    float*  hrow = (float*)(sm4 + 2*128*12);  // 2*128*24 floats
    __shared__ float2 tw[128];
    int tid = threadIdx.x;
    if (tid < 128) tw[tid] = d_tw[tid];
    int row0 = blockIdx.x * 2;

    // load previous h (2 contiguous rows) for the 1x1 conv
    {
        const float4* hsrc4 = (const float4*)(d_h + (size_t)row0 * YY * WW);
        float4* hrow4 = (float4*)hrow;
        #pragma unroll
        for (int k = 0; k < 6; k++) hrow4[tid + k*256] = hsrc4[tid + k*256];
    }

    // streaming pack: Z[k] = A + iB (Hermitian fold, DC/Nyq imag drop) -> A4
    {
        const float4* spec4 = (const float4*)(d_spec + (size_t)row0 * YHH * WW);
        #pragma unroll
        for (int it = 0; it < 6; it++) {
            int idx = tid + it*256;           // k*12 + lp
            int k = idx / 12, lp = idx % 12;
            int r = lp / 6, cp = lp % 6;
            const float4* sp = spec4 + (size_t)r * YHH * 12;
            float2 z0, z1;
            if (k == 0 || k == 64) {
                float4 v0 = sp[k*12 + 2*cp], v1 = sp[k*12 + 2*cp + 1];
                z0 = make_float2(v0.x, v0.z);
                z1 = make_float2(v1.x, v1.z);
            } else if (k < 64) {
                float4 v0 = sp[k*12 + 2*cp], v1 = sp[k*12 + 2*cp + 1];
                z0 = make_float2(v0.x - v0.w, v0.y + v0.z);
                z1 = make_float2(v1.x - v1.w, v1.y + v1.z);
            } else {
                float4 v0 = sp[(128-k)*12 + 2*cp], v1 = sp[(128-k)*12 + 2*cp + 1];
                z0 = make_float2(v0.x + v0.w, v0.z - v0.y);
                z1 = make_float2(v1.x + v1.w, v1.z - v1.y);
            }
            A4[idx] = make_float4(z0.x, z0.y, z1.x, z1.y);
        }
    }
    __syncthreads();   // tw + hrow + packed A4 all visible

    // inverse y-FFT: A4 -> (B,A ping-pong) -> R in B4
    auto ldz = [&](int p, int lp) { return A4[p*12 + lp]; };
    auto stR = [&](int p, int lp, float4 v) { B4[p*12 + lp] = v; };
    fft128_io<12,true,256>(B4, A4, tid, tw, ldz, stR);
    __syncthreads();

    // conv + relu; R=B4 -> packed h_new pairs P=A4 and global d_h
    const float* cw = conv_w + layer * IOSZ;
    const float* cb = conv_b + layer * WW;
    const float2* R2 = (const float2*)B4;     // [y*24 + r*12 + c]
    float2* P2 = (float2*)A4;
    #pragma unroll 2
    for (int idx = tid; idx < 2*128*12; idx += 256) {
        int y = idx / 24, l = idx % 24;
        int r = l / 12, c = l % 12, o = 2*c;
        float2 z = R2[idx];
        float acc0 = cb[o], acc1 = cb[o+1];
        const float* hr = hrow + r*YY*WW + y*WW;
        #pragma unroll
        for (int i = 0; i < WW; i++) {
            float hv = hr[i];
            float2 w = __ldg((const float2*)(cw + i*WW + o));
            acc0 += hv * w.x;
            acc1 += hv * w.y;
        }
        float hn0 = fmaxf(z.x * (1.0f/16384.0f), 0.0f) + acc0;
        float hn1 = fmaxf(z.y * (1.0f/16384.0f), 0.0f) + acc1;
        P2[idx] = make_float2(hn0, hn1);
        ((float2*)(d_h + (size_t)(row0 + r) * YY * WW))[y*12 + c] =
            make_float2(hn0, hn1);
    }
    __syncthreads();

    if (flags & 1) {   // out mapping (COUT = 1); reads P=A4 (safe: fwd FFT's
        int r = tid >> 7, y = tid & 127;      // first A4 write is stage 2,
        int row = row0 + r;                   // behind the stage-1 barrier)
        int b = row >> 7, xs = row & 127;
        float s = out_b[0];
        #pragma unroll
        for (int c = 0; c < 12; c++) {
            float2 z = P2[y*24 + r*12 + c];
            s += z.x * __ldg(out_w + 2*c) + z.y * __ldg(out_w + 2*c + 1);
        }
        outp[(((size_t)b*Trt + t)*XX + xs)*YY + y] = s;
    }

    if (flags & 2) {   // forward rfft-y of P=A4 -> Z in B4, then unscramble
        auto ldP = [&](int p, int lp) { return A4[p*12 + lp]; };
        auto stZ = [&](int p, int lp, float4 v) { B4[p*12 + lp] = v; };
        fft128_io<12,false,256>(B4, A4, tid, tw, ldP, stZ);
        __syncthreads();
        const float2* Z2 = (const float2*)B4;
        float4* hfo = (float4*)(d_hf + (size_t)row0 * YHH * WW);
        #pragma unroll 2
        for (int idx = tid; idx < YHH*24; idx += 256) {
            int k = idx / 24, l = idx % 24;
            int r = l / 12, c = l % 12;
            float2 Zk = Z2[k*24 + l];
            float2 Zm = Z2[((128 - k) & 127)*24 + l];
            // A = (Z[k] + conj(Z[-k]))/2 ; B = (Z[k] - conj(Z[-k]))/(2i)
            float ax = 0.5f*(Zk.x + Zm.x), ay = 0.5f*(Zk.y - Zm.y);
            float bx = 0.5f*(Zk.y + Zm.y), by = 0.5f*(Zm.x - Zk.x);
            hfo[((size_t)r*YHH + k)*12 + c] = make_float4(ax, ay, bx, by);
        }
    }
}

// ---------------- host launcher ----------------------------------------------
extern "C" void kernel_launch(void* const* d_in, const int* in_sizes, int n_in,
                              void* d_out, int out_size) {
    const float* x      = (const float*)d_in[0];
    const float* in_w   = (const float*)d_in[1];
    const float* in_b   = (const float*)d_in[2];
    const float* spec_w = (const float*)d_in[3];
    const float* conv_w = (const float*)d_in[4];
    const float* conv_b = (const float*)d_in[5];
    const float* out_w  = (const float*)d_in[6];
    const float* out_b  = (const float*)d_in[7];
    float* outp = (float*)d_out;
    int Trt = out_size / (BB * XX * YY);

    const int SMEM_ROW  = 2 * 128 * 12 * (int)sizeof(float4);     // 49152
    const int SMEM_SPEC = 2 * 128 * 24 * (int)sizeof(float4);     // 98304
    const int SMEM_UPD  = 2 * 128 * 12 * (int)sizeof(float4)
                        + 2 * 128 * WW * (int)sizeof(float);      // 73728
    cudaFuncSetAttribute(k_spectral, cudaFuncAttributeMaxDynamicSharedMemorySize, SMEM_SPEC);
    cudaFuncSetAttribute(k_rfft_y,   cudaFuncAttributeMaxDynamicSharedMemorySize, SMEM_ROW);
    cudaFuncSetAttribute(k_update,   cudaFuncAttributeMaxDynamicSharedMemorySize, SMEM_UPD);

    k_twiddle<<<1, 128>>>();

    dim3 tb(32, 8), tg(NFREQ/32, IOSZ/32, DD);
    k_transpose<<<tg, tb>>>((const float2*)spec_w);

    k_inmap<<<(NPIX + 255)/256, 256>>>(x, in_w, in_b);
    k_rfft_y<<<NROWS, 512, SMEM_ROW>>>();

    for (int t = 0; t < Trt; t++) {
        for (int d = 0; d < DD; d++) {
            k_spectral<<<4*YHH, 512, SMEM_SPEC>>>(d);
            int flags = (d == DD-1 ? 1 : 0)
                      | ((t == Trt-1 && d == DD-1) ? 0 : 2);
            k_update<<<NROWS/2, 256, SMEM_UPD>>>(d, t, Trt, flags,
                                                 conv_w, conv_b, out_w, out_b, outp);
        }
    }
}

// round 11
// speedup vs baseline: 1.0663x; 1.0663x over previous
#include <cuda_runtime.h>
#include <math.h>

#define BB 8
#define XX 128
#define YY 128
#define WW 24
#define DD 4
#define YHH 65
#define NPIX (BB*XX*YY)        // 131072
#define NROWS (BB*XX)          // 1024
#define NFREQ (XX*YHH)         // 8320
#define IOSZ (WW*WW)           // 576

// ---------------- device scratch (static: no allocations allowed) ------------
__device__ float  d_h[(size_t)NPIX*WW];             // (B,X,Y,W)      12.6 MB
__device__ float2 d_hf[(size_t)NROWS*YHH*WW];       // (B,X,YH,W)     12.8 MB
__device__ float2 d_spec[(size_t)NROWS*YHH*WW];     // (B,X,YH,W)     12.8 MB
__device__ float2 d_wt[(size_t)DD*NFREQ*IOSZ];      // (D,f,i,o)     153.4 MB
__device__ float2 d_tw[128];                        // exp(-i*pi*k/64)

__device__ __forceinline__ float4 cmul4(float4 v, float2 w) {
    return make_float4(v.x*w.x - v.y*w.y, v.x*w.y + v.y*w.x,
                       v.z*w.x - v.w*w.y, v.z*w.y + v.w*w.x);
}
__device__ __forceinline__ float4 add4(float4 a, float4 b) {
    return make_float4(a.x+b.x, a.y+b.y, a.z+b.z, a.w+b.w);
}
__device__ __forceinline__ float4 sub4(float4 a, float4 b) {
    return make_float4(a.x-b.x, a.y-b.y, a.z-b.z, a.w-b.w);
}
// fwd: multiply both packed complex by -j ; inv: by +j
template<bool INV>
__device__ __forceinline__ float4 mulj4(float4 v) {
    return INV ? make_float4(-v.y, v.x, -v.w, v.z)
               : make_float4( v.y,-v.x,  v.w,-v.z);
}

// ---------------- twiddle table ----------------------------------------------
__global__ void k_twiddle() {
    int k = threadIdx.x;
    double s, c;
    sincospi(-(double)k / 64.0, &s, &c);
    d_tw[k] = make_float2((float)c, (float)s);
}

// ---------------- weight transpose: (d, io, f) -> (d, f, io) ------------------
__global__ void k_transpose(const float2* __restrict__ src) {
    __shared__ float2 tile[32][33];
    int dd  = blockIdx.z;
    int f0  = blockIdx.x * 32;
    int io0 = blockIdx.y * 32;
    const float2* s = src + (size_t)dd * IOSZ * NFREQ;
    #pragma unroll
    for (int j = 0; j < 4; j++) {
        int io = io0 + threadIdx.y + j*8;
        int f  = f0 + threadIdx.x;
        tile[threadIdx.y + j*8][threadIdx.x] = s[(size_t)io * NFREQ + f];
    }
    __syncthreads();
    float2* dst = d_wt + (size_t)dd * NFREQ * IOSZ;
    #pragma unroll
    for (int j = 0; j < 4; j++) {
        int f  = f0 + threadIdx.y + j*8;
        int io = io0 + threadIdx.x;
        dst[(size_t)f * IOSZ + io] = tile[threadIdx.x][threadIdx.y + j*8];
    }
}

// ---------------- 128-point Stockham FFT, radix 4*4*8, fused I/O --------------
// LP float4 lanes per point (2 complex lines each). Layout buf[point*LP + lp].
// Stage 1 reads via ld(point, lp); stage 3 writes via st(point, lp, val).
// s1: ld -> b0; sync; s2: b0 -> b1; sync; s3: b1 -> st. NO trailing sync.
// The buffer ld reads from may alias b1 (stage 2 clobbers it only after the
// stage-1 barrier); st may alias b0 (consumed by stage 2 before the barrier).
template<int LP, bool INV, int NT, class LD, class ST>
__device__ __forceinline__ void fft128_io(float4* b0, float4* b1, int tid,
                                          const float2* __restrict__ tw,
                                          LD ld, ST st) {
    // -------- stage 1: radix-4, s=1 --------
    #pragma unroll 2
    for (int idx = tid; idx < 32*LP; idx += NT) {
        int lp = idx % LP;
        int p  = idx / LP;                     // 0..31
        float4 a = ld(p,      lp);
        float4 b = ld(p + 32, lp);
        float4 c = ld(p + 64, lp);
        float4 d = ld(p + 96, lp);
        float2 w1 = tw[p], w2 = tw[2*p], w3 = tw[3*p];
        if (INV) { w1.y = -w1.y; w2.y = -w2.y; w3.y = -w3.y; }
        float4 apc = add4(a, c), amc = sub4(a, c);
        float4 bpd = add4(b, d), bmd = sub4(b, d);
        float4 jb  = mulj4<INV>(bmd);
        int ob = 4*p;
        b0[(ob    )*LP + lp] = add4(apc, bpd);
        b0[(ob + 1)*LP + lp] = cmul4(add4(amc, jb), w1);
        b0[(ob + 2)*LP + lp] = cmul4(sub4(apc, bpd), w2);
        b0[(ob + 3)*LP + lp] = cmul4(sub4(amc, jb), w3);
    }
    __syncthreads();
    // -------- stage 2: radix-4, s=4 --------
    #pragma unroll 2
    for (int idx = tid; idx < 32*LP; idx += NT) {
        int lp = idx % LP;
        int bf = idx / LP;
        int q = bf & 3, p = bf >> 2;           // p 0..7
        int base = q + 4*p;
        float4 a = b0[ base      *LP + lp];
        float4 b = b0[(base+32 )*LP + lp];
        float4 c = b0[(base+64 )*LP + lp];
        float4 d = b0[(base+96 )*LP + lp];
        float2 w1 = tw[4*p], w2 = tw[8*p], w3 = tw[12*p];
        if (INV) { w1.y = -w1.y; w2.y = -w2.y; w3.y = -w3.y; }
        float4 apc = add4(a, c), amc = sub4(a, c);
        float4 bpd = add4(b, d), bmd = sub4(b, d);
        float4 jb  = mulj4<INV>(bmd);
        int ob = q + 16*p;
        b1[(ob     )*LP + lp] = add4(apc, bpd);
        b1[(ob + 4 )*LP + lp] = cmul4(add4(amc, jb), w1);
        b1[(ob + 8 )*LP + lp] = cmul4(sub4(apc, bpd), w2);
        b1[(ob + 12)*LP + lp] = cmul4(sub4(amc, jb), w3);
    }
    __syncthreads();
    // -------- stage 3: radix-8, s=16, p=0 (no table twiddles) --------
    const float C = 0.70710678118654752f;
    #pragma unroll 2
    for (int idx = tid; idx < 16*LP; idx += NT) {
        int lp = idx % LP;
        int q  = idx / LP;                     // 0..15
        float4 x0 = b1[(q       )*LP + lp];
        float4 x1 = b1[(q + 16 )*LP + lp];
        float4 x2 = b1[(q + 32 )*LP + lp];
        float4 x3 = b1[(q + 48 )*LP + lp];
        float4 x4 = b1[(q + 64 )*LP + lp];
        float4 x5 = b1[(q + 80 )*LP + lp];
        float4 x6 = b1[(q + 96 )*LP + lp];
        float4 x7 = b1[(q + 112)*LP + lp];
        float4 t0 = add4(x0, x4), t1 = sub4(x0, x4);
        float4 t2 = add4(x2, x6), t3 = sub4(x2, x6);
        float4 jt3 = mulj4<INV>(t3);
        float4 e0 = add4(t0, t2), e2 = sub4(t0, t2);
        float4 e1 = add4(t1, jt3), e3 = sub4(t1, jt3);
        float4 u0 = add4(x1, x5), u1 = sub4(x1, x5);
        float4 u2 = add4(x3, x7), u3 = sub4(x3, x7);
        float4 ju3 = mulj4<INV>(u3);
        float4 o0 = add4(u0, u2), o2 = sub4(u0, u2);
        float4 o1 = add4(u1, ju3), o3 = sub4(u1, ju3);
        float2 w81 = INV ? make_float2( C,  C) : make_float2( C, -C);
        float2 w83 = INV ? make_float2(-C,  C) : make_float2(-C, -C);
        float4 o1w = cmul4(o1, w81);
        float4 o2w = mulj4<INV>(o2);
        float4 o3w = cmul4(o3, w83);
        st(q      , lp, add4(e0, o0));
        st(q + 16 , lp, add4(e1, o1w));
        st(q + 32 , lp, add4(e2, o2w));
        st(q + 48 , lp, add4(e3, o3w));
        st(q + 64 , lp, sub4(e0, o0));
        st(q + 80 , lp, sub4(e1, o1w));
        st(q + 96 , lp, sub4(e2, o2w));
        st(q + 112, lp, sub4(e3, o3w));
    }
}

// ---------------- in mapping ---------------------------------------------------
__global__ void k_inmap(const float* __restrict__ x,
                        const float* __restrict__ iw,
                        const float* __restrict__ ib) {
    int p = blockIdx.x * blockDim.x + threadIdx.x;
    if (p >= NPIX) return;
    float a = x[2*p], b = x[2*p + 1];
    float* out = d_h + (size_t)p * WW;
    #pragma unroll
    for (int w = 0; w < WW; w++)
        out[w] = a*iw[w] + b*iw[WW + w] + ib[w];
}

// ---------------- rfft along y per (b,x) row (runs once; fully fused I/O) -----
__global__ void k_rfft_y() {
    extern __shared__ float4 sm4[];
    float4* bufA = sm4;                 // 128*12
    float4* bufB = sm4 + 128*12;
    __shared__ float2 tw[128];
    int tid = threadIdx.x;
    if (tid < 128) tw[tid] = d_tw[tid];
    __syncthreads();
    int row = blockIdx.x;
    const float* hsrc = d_h + (size_t)row * YY * WW;
    float4* hfo = (float4*)(d_hf + (size_t)row * YHH * WW);
    auto ld = [&](int p, int lp) {
        return make_float4(hsrc[p*24 + 2*lp], 0.0f, hsrc[p*24 + 2*lp + 1], 0.0f);
    };
    auto st = [&](int p, int lp, float4 v) {
        if (p < YHH) hfo[p*12 + lp] = v;
    };
    fft128_io<12,false,512>(bufA, bufB, tid, tw, ld, st);
}

// ---------------- fused fft-x + spectral matmul + ifft-x ----------------------
// block = (yh, batch-pair of 2). 48 lines = 24 float4 lanes. smem 96KB, 2 CTA/SM
// Streaming preload for the forward input; fused smem store for the forward
// output; fused global scatter for the inverse output.
__global__ __launch_bounds__(512) void k_spectral(int layer) {
    extern __shared__ float4 sm4[];
    float4* bufA = sm4;                 // 128*24
    float4* bufB = sm4 + 128*24;
    __shared__ float2 tw[128];
    int tid = threadIdx.x;
    if (tid < 128) tw[tid] = d_tw[tid];
    int yh  = blockIdx.x >> 2;
    int b0i = (blockIdx.x & 3) * 2;

    // streaming preload hf -> bufA (6 independent float4 LDGs per thread)
    {
        const float4* hf4 = (const float4*)d_hf;
        #pragma unroll
        for (int k = 0; k < 6; k++) {
            int idx = tid + k*512;
            int x = idx / 24, l = idx % 24;
            int b = b0i + l/12, ip = l % 12;
            bufA[idx] = hf4[(((size_t)b*XX + x)*YHH + yh)*12 + ip];
        }
    }
    __syncthreads();

    // forward x-FFT: bufA -> (B,A ping-pong) -> F in bufB
    auto ldf = [&](int p, int lp) { return bufA[p*24 + lp]; };
    auto stf = [&](int p, int lp, float4 v) { bufB[p*24 + lp] = v; };
    fft128_io<24,false,512>(bufB, bufA, tid, tw, ldf, stf);
    __syncthreads();

    // yf[b][o] = sum_i hf[b][i] * w[i][o]; F=bufB -> G=bufA
    const float2* wt = d_wt + (size_t)layer * NFREQ * IOSZ;
    const float2* F = (const float2*)bufB;
    float4* G4 = bufA;
    #pragma unroll 2
    for (int j = tid; j < 128*12; j += 512) {
        int x = j / 12, op = j % 12, o = op * 2;
        const float4* wp4 = (const float4*)(wt + ((size_t)x*YHH + yh)*IOSZ + o);
        const float2* hp  = F + x*48;
        float2 a00 = {0,0}, a01 = {0,0}, a10 = {0,0}, a11 = {0,0};
        #pragma unroll
        for (int i = 0; i < WW; i++) {
            float4 w4 = __ldg(wp4 + i*12);           // w[i][o], w[i][o+1]
            float2 w0 = make_float2(w4.x, w4.y);
            float2 w1 = make_float2(w4.z, w4.w);
            float2 h0 = hp[i], h1 = hp[24+i];
            a00.x += h0.x*w0.x - h0.y*w0.y;  a00.y += h0.x*w0.y + h0.y*w0.x;
            a01.x += h0.x*w1.x - h0.y*w1.y;  a01.y += h0.x*w1.y + h0.y*w1.x;
            a10.x += h1.x*w0.x - h1.y*w0.y;  a10.y += h1.x*w0.y + h1.y*w0.x;
            a11.x += h1.x*w1.x - h1.y*w1.y;  a11.y += h1.x*w1.y + h1.y*w1.x;
        }
        G4[(x*48 + o) >> 1]      = make_float4(a00.x, a00.y, a01.x, a01.y);
        G4[(x*48 + 24 + o) >> 1] = make_float4(a10.x, a10.y, a11.x, a11.y);
    }
    __syncthreads();

    // inverse x-FFT: G=bufA -> (B,A ping-pong) -> scatter to d_spec
    float4* sp4 = (float4*)d_spec;
    auto ldi = [&](int p, int lp) { return bufA[p*24 + lp]; };
    auto sti = [&](int p, int lp, float4 v) {
        int b = b0i + lp/12, ip = lp % 12;
        sp4[(((size_t)b*XX + p)*YHH + yh)*12 + ip] = v;
    };
    fft128_io<24,true,512>(bufB, bufA, tid, tw, ldi, sti);
}

// ---------------- fused irfft-y + 1x1 conv + relu (+ out-map) (+ next rfft-y) -
// ONE row per block, 512 threads, 36.8KB smem -> 4 CTA/SM (64 warps/SM).
// Channel-pair packing: 12 complex lines (= 6 float4 lanes) carry 24 channels.
// irfft semantics: DC/Nyquist imaginary parts are ignored -> dropped on pack.
__global__ __launch_bounds__(512) void k_update(int layer, int t, int Trt, int flags,
                         const float* __restrict__ conv_w,
                         const float* __restrict__ conv_b,
                         const float* __restrict__ out_w,
                         const float* __restrict__ out_b,
                         float* __restrict__ outp) {
    extern __shared__ float4 sm4[];
    float4* A4  = sm4;                        // 128*6 float4 = 12 complex lines
    float4* B4  = sm4 + 128*6;
    float*  hrow = (float*)(sm4 + 2*128*6);   // 128*24 floats
    __shared__ float2 tw[128];
    int tid = threadIdx.x;
    if (tid < 128) tw[tid] = d_tw[tid];
    int row = blockIdx.x;                 // b*128 + x

    // load previous h (for 1x1 conv) — independent stream, issue first
    {
        const float4* hsrc4 = (const float4*)(d_h + (size_t)row * YY * WW);
        float4* hrow4 = (float4*)hrow;
        for (int i = tid; i < YY*WW/4; i += 512) hrow4[i] = hsrc4[i];
    }

    // streaming pack: Z[k] = A + iB (Hermitian fold, DC/Nyq imag drop) -> A4
    {
        const float4* sp = (const float4*)(d_spec + (size_t)row * YHH * WW);
        for (int idx = tid; idx < 128*6; idx += 512) {
            int k = idx / 6, cp = idx % 6;
            float2 z0, z1;
            if (k == 0 || k == 64) {
                float4 v0 = sp[k*12 + 2*cp], v1 = sp[k*12 + 2*cp + 1];
                z0 = make_float2(v0.x, v0.z);
                z1 = make_float2(v1.x, v1.z);
            } else if (k < 64) {
                float4 v0 = sp[k*12 + 2*cp], v1 = sp[k*12 + 2*cp + 1];
                z0 = make_float2(v0.x - v0.w, v0.y + v0.z);
                z1 = make_float2(v1.x - v1.w, v1.y + v1.z);
            } else {
                float4 v0 = sp[(128-k)*12 + 2*cp], v1 = sp[(128-k)*12 + 2*cp + 1];
                z0 = make_float2(v0.x + v0.w, v0.z - v0.y);
                z1 = make_float2(v1.x + v1.w, v1.z - v1.y);
            }
            A4[idx] = make_float4(z0.x, z0.y, z1.x, z1.y);
        }
    }
    __syncthreads();   // tw + hrow + packed A4 all visible

    // inverse y-FFT: A4 -> (B4,A4 ping-pong) -> R in B4
    auto ldz = [&](int p, int lp) { return A4[p*6 + lp]; };
    auto stR = [&](int p, int lp, float4 v) { B4[p*6 + lp] = v; };
    fft128_io<6,true,512>(B4, A4, tid, tw, ldz, stR);
    __syncthreads();

    // conv + relu; R=B4 -> packed h_new pairs P=A4 and global d_h
    const float* cw = conv_w + layer * IOSZ;
    const float* cb = conv_b + layer * WW;
    const float2* R2 = (const float2*)B4;     // [y*12 + c]
    float2* P2 = (float2*)A4;
    float2* hdst2 = (float2*)(d_h + (size_t)row * YY * WW);
    #pragma unroll 2
    for (int idx = tid; idx < 128*12; idx += 512) {
        int y = idx / 12, c = idx % 12, o = 2*c;
        float2 z = R2[idx];
        float acc0 = cb[o], acc1 = cb[o+1];
        const float* hr = hrow + y*WW;
        #pragma unroll
        for (int i = 0; i < WW; i++) {
            float hv = hr[i];
            float2 w = __ldg((const float2*)(cw + i*WW + o));
            acc0 += hv * w.x;
            acc1 += hv * w.y;
        }
        float hn0 = fmaxf(z.x * (1.0f/16384.0f), 0.0f) + acc0;
        float hn1 = fmaxf(z.y * (1.0f/16384.0f), 0.0f) + acc1;
        P2[idx] = make_float2(hn0, hn1);
        hdst2[y*12 + c] = make_float2(hn0, hn1);
    }
    __syncthreads();

    if (flags & 1) {   // out mapping (COUT = 1); reads P=A4 (safe: fwd FFT's
        int b = row >> 7, xs = row & 127;     // first A4 write is stage 2,
        float ob0 = out_b[0];                 // behind the stage-1 barrier)
        for (int y = tid; y < YY; y += 512) {
            float s = ob0;
            #pragma unroll
            for (int c = 0; c < 12; c++) {
                float2 z = P2[y*12 + c];
                s += z.x * __ldg(out_w + 2*c) + z.y * __ldg(out_w + 2*c + 1);
            }
            outp[(((size_t)b*Trt + t)*XX + xs)*YY + y] = s;
        }
    }

    if (flags & 2) {   // forward rfft-y of P=A4 -> Z in B4, then unscramble
        auto ldP = [&](int p, int lp) { return A4[p*6 + lp]; };
        auto stZ = [&](int p, int lp, float4 v) { B4[p*6 + lp] = v; };
        fft128_io<6,false,512>(B4, A4, tid, tw, ldP, stZ);
        __syncthreads();
        const float2* Z2 = (const float2*)B4;
        float4* hfo = (float4*)(d_hf + (size_t)row * YHH * WW);
        #pragma unroll 2
        for (int idx = tid; idx < YHH*12; idx += 512) {
            int k = idx / 12, c = idx % 12;
            float2 Zk = Z2[k*12 + c];
            float2 Zm = Z2[((128 - k) & 127)*12 + c];
            // A = (Z[k] + conj(Z[-k]))/2 ; B = (Z[k] - conj(Z[-k]))/(2i)
            float ax = 0.5f*(Zk.x + Zm.x), ay = 0.5f*(Zk.y - Zm.y);
            float bx = 0.5f*(Zk.y + Zm.y), by = 0.5f*(Zm.x - Zk.x);
            hfo[k*12 + c] = make_float4(ax, ay, bx, by);
        }
    }
}

// ---------------- host launcher ----------------------------------------------
extern "C" void kernel_launch(void* const* d_in, const int* in_sizes, int n_in,
                              void* d_out, int out_size) {
    const float* x      = (const float*)d_in[0];
    const float* in_w   = (const float*)d_in[1];
    const float* in_b   = (const float*)d_in[2];
    const float* spec_w = (const float*)d_in[3];
    const float* conv_w = (const float*)d_in[4];
    const float* conv_b = (const float*)d_in[5];
    const float* out_w  = (const float*)d_in[6];
    const float* out_b  = (const float*)d_in[7];
    float* outp = (float*)d_out;
    int Trt = out_size / (BB * XX * YY);

    const int SMEM_ROW  = 2 * 128 * 12 * (int)sizeof(float4);     // 49152
    const int SMEM_SPEC = 2 * 128 * 24 * (int)sizeof(float4);     // 98304
    const int SMEM_UPD  = 2 * 128 * 6 * (int)sizeof(float4)
                        + 128 * WW * (int)sizeof(float);          // 36864
    cudaFuncSetAttribute(k_spectral, cudaFuncAttributeMaxDynamicSharedMemorySize, SMEM_SPEC);
    cudaFuncSetAttribute(k_rfft_y,   cudaFuncAttributeMaxDynamicSharedMemorySize, SMEM_ROW);
    cudaFuncSetAttribute(k_update,   cudaFuncAttributeMaxDynamicSharedMemorySize, SMEM_UPD);

    k_twiddle<<<1, 128>>>();

    dim3 tb(32, 8), tg(NFREQ/32, IOSZ/32, DD);
    k_transpose<<<tg, tb>>>((const float2*)spec_w);

    k_inmap<<<(NPIX + 255)/256, 256>>>(x, in_w, in_b);
    k_rfft_y<<<NROWS, 512, SMEM_ROW>>>();

    for (int t = 0; t < Trt; t++) {
        for (int d = 0; d < DD; d++) {
            k_spectral<<<4*YHH, 512, SMEM_SPEC>>>(d);
            int flags = (d == DD-1 ? 1 : 0)
                      | ((t == Trt-1 && d == DD-1) ? 0 : 2);
            k_update<<<NROWS, 512, SMEM_UPD>>>(d, t, Trt, flags,
                                               conv_w, conv_b, out_w, out_b, outp);
        }
    }
}

// round 15
// speedup vs baseline: 1.0979x; 1.0296x over previous
#include <cuda_runtime.h>
#include <math.h>

#define BB 8
#define XX 128
#define YY 128
#define WW 24
#define DD 4
#define YHH 65
#define NPIX (BB*XX*YY)        // 131072
#define NROWS (BB*XX)          // 1024
#define NFREQ (XX*YHH)         // 8320
#define IOSZ (WW*WW)           // 576

// ---------------- device scratch (static: no allocations allowed) ------------
__device__ float  d_h[(size_t)NPIX*WW];             // (B,X,Y,W)      12.6 MB
__device__ float2 d_z[(size_t)NROWS*128*12];        // packed y-spectra 12.6 MB
__device__ float2 d_spec[(size_t)NROWS*YHH*WW];     // (B,X,YH,W)     12.8 MB
__device__ float2 d_wt[(size_t)DD*NFREQ*IOSZ];      // (D,f,i,o)     153.4 MB
__device__ float2 d_tw[128];                        // exp(-i*pi*k/64)

__device__ __forceinline__ float4 cmul4(float4 v, float2 w) {
    return make_float4(v.x*w.x - v.y*w.y, v.x*w.y + v.y*w.x,
                       v.z*w.x - v.w*w.y, v.z*w.y + v.w*w.x);
}
__device__ __forceinline__ float4 add4(float4 a, float4 b) {
    return make_float4(a.x+b.x, a.y+b.y, a.z+b.z, a.w+b.w);
}
__device__ __forceinline__ float4 sub4(float4 a, float4 b) {
    return make_float4(a.x-b.x, a.y-b.y, a.z-b.z, a.w-b.w);
}
template<bool INV>
__device__ __forceinline__ float4 mulj4(float4 v) {
    return INV ? make_float4(-v.y, v.x, -v.w, v.z)
               : make_float4( v.y,-v.x,  v.w,-v.z);
}

// ---------------- twiddle table ----------------------------------------------
__global__ void k_twiddle() {
    int k = threadIdx.x;
    double s, c;
    sincospi(-(double)k / 64.0, &s, &c);
    d_tw[k] = make_float2((float)c, (float)s);
}

// ---------------- weight transpose: (d, io, f) -> (d, f, io) ------------------
__global__ void k_transpose(const float2* __restrict__ src) {
    __shared__ float2 tile[32][33];
    int dd  = blockIdx.z;
    int f0  = blockIdx.x * 32;
    int io0 = blockIdx.y * 32;
    const float2* s = src + (size_t)dd * IOSZ * NFREQ;
    #pragma unroll
    for (int j = 0; j < 4; j++) {
        int io = io0 + threadIdx.y + j*8;
        int f  = f0 + threadIdx.x;
        tile[threadIdx.y + j*8][threadIdx.x] = s[(size_t)io * NFREQ + f];
    }
    __syncthreads();
    float2* dst = d_wt + (size_t)dd * NFREQ * IOSZ;
    #pragma unroll
    for (int j = 0; j < 4; j++) {
        int f  = f0 + threadIdx.y + j*8;
        int io = io0 + threadIdx.x;
        dst[(size_t)f * IOSZ + io] = tile[threadIdx.x][threadIdx.y + j*8];
    }
}

// ---------------- 128-point Stockham FFT, radix 4*4*8, fused I/O --------------
// LP float4 lanes per point (2 complex lines each). Layout buf[point*LP + lp].
// s1: ld -> b0; sync; s2: b0 -> b1; sync; s3: b1 -> st. NO trailing sync.
// ld may alias b1 (stage 2 clobbers only after the stage-1 barrier);
// st may alias b0 (consumed by stage 2 before the barrier).
template<int LP, bool INV, int NT, class LD, class ST>
__device__ __forceinline__ void fft128_io(float4* b0, float4* b1, int tid,
                                          const float2* __restrict__ tw,
                                          LD ld, ST st) {
    // -------- stage 1: radix-4, s=1 --------
    #pragma unroll 2
    for (int idx = tid; idx < 32*LP; idx += NT) {
        int lp = idx % LP;
        int p  = idx / LP;
        float4 a = ld(p,      lp);
        float4 b = ld(p + 32, lp);
        float4 c = ld(p + 64, lp);
        float4 d = ld(p + 96, lp);
        float2 w1 = tw[p], w2 = tw[2*p], w3 = tw[3*p];
        if (INV) { w1.y = -w1.y; w2.y = -w2.y; w3.y = -w3.y; }
        float4 apc = add4(a, c), amc = sub4(a, c);
        float4 bpd = add4(b, d), bmd = sub4(b, d);
        float4 jb  = mulj4<INV>(bmd);
        int ob = 4*p;
        b0[(ob    )*LP + lp] = add4(apc, bpd);
        b0[(ob + 1)*LP + lp] = cmul4(add4(amc, jb), w1);
        b0[(ob + 2)*LP + lp] = cmul4(sub4(apc, bpd), w2);
        b0[(ob + 3)*LP + lp] = cmul4(sub4(amc, jb), w3);
    }
    __syncthreads();
    // -------- stage 2: radix-4, s=4 --------
    #pragma unroll 2
    for (int idx = tid; idx < 32*LP; idx += NT) {
        int lp = idx % LP;
        int bf = idx / LP;
        int q = bf & 3, p = bf >> 2;
        int base = q + 4*p;
        float4 a = b0[ base      *LP + lp];
        float4 b = b0[(base+32 )*LP + lp];
        float4 c = b0[(base+64 )*LP + lp];
        float4 d = b0[(base+96 )*LP + lp];
        float2 w1 = tw[4*p], w2 = tw[8*p], w3 = tw[12*p];
        if (INV) { w1.y = -w1.y; w2.y = -w2.y; w3.y = -w3.y; }
        float4 apc = add4(a, c), amc = sub4(a, c);
        float4 bpd = add4(b, d), bmd = sub4(b, d);
        float4 jb  = mulj4<INV>(bmd);
        int ob = q + 16*p;
        b1[(ob     )*LP + lp] = add4(apc, bpd);
        b1[(ob + 4 )*LP + lp] = cmul4(add4(amc, jb), w1);
        b1[(ob + 8 )*LP + lp] = cmul4(sub4(apc, bpd), w2);
        b1[(ob + 12)*LP + lp] = cmul4(sub4(amc, jb), w3);
    }
    __syncthreads();
    // -------- stage 3: radix-8, s=16, p=0 --------
    const float C = 0.70710678118654752f;
    #pragma unroll 2
    for (int idx = tid; idx < 16*LP; idx += NT) {
        int lp = idx % LP;
        int q  = idx / LP;
        float4 x0 = b1[(q       )*LP + lp];
        float4 x1 = b1[(q + 16 )*LP + lp];
        float4 x2 = b1[(q + 32 )*LP + lp];
        float4 x3 = b1[(q + 48 )*LP + lp];
        float4 x4 = b1[(q + 64 )*LP + lp];
        float4 x5 = b1[(q + 80 )*LP + lp];
        float4 x6 = b1[(q + 96 )*LP + lp];
        float4 x7 = b1[(q + 112)*LP + lp];
        float4 t0 = add4(x0, x4), t1 = sub4(x0, x4);
        float4 t2 = add4(x2, x6), t3 = sub4(x2, x6);
        float4 jt3 = mulj4<INV>(t3);
        float4 e0 = add4(t0, t2), e2 = sub4(t0, t2);
        float4 e1 = add4(t1, jt3), e3 = sub4(t1, jt3);
        float4 u0 = add4(x1, x5), u1 = sub4(x1, x5);
        float4 u2 = add4(x3, x7), u3 = sub4(x3, x7);
        float4 ju3 = mulj4<INV>(u3);
        float4 o0 = add4(u0, u2), o2 = sub4(u0, u2);
        float4 o1 = add4(u1, ju3), o3 = sub4(u1, ju3);
        float2 w81 = INV ? make_float2( C,  C) : make_float2( C, -C);
        float2 w83 = INV ? make_float2(-C,  C) : make_float2(-C, -C);
        float4 o1w = cmul4(o1, w81);
        float4 o2w = mulj4<INV>(o2);
        float4 o3w = cmul4(o3, w83);
        st(q      , lp, add4(e0, o0));
        st(q + 16 , lp, add4(e1, o1w));
        st(q + 32 , lp, add4(e2, o2w));
        st(q + 48 , lp, add4(e3, o3w));
        st(q + 64 , lp, sub4(e0, o0));
        st(q + 80 , lp, sub4(e1, o1w));
        st(q + 96 , lp, sub4(e2, o2w));
        st(q + 112, lp, sub4(e3, o3w));
    }
}

// ---------------- in mapping ---------------------------------------------------
__global__ void k_inmap(const float* __restrict__ x,
                        const float* __restrict__ iw,
                        const float* __restrict__ ib) {
    int p = blockIdx.x * blockDim.x + threadIdx.x;
    if (p >= NPIX) return;
    float a = x[2*p], b = x[2*p + 1];
    float* out = d_h + (size_t)p * WW;
    #pragma unroll
    for (int w = 0; w < WW; w++)
        out[w] = a*iw[w] + b*iw[WW + w] + ib[w];
}

// ---------------- packed rfft-y per row (runs once) ---------------------------
// Channel-pair packing: line c = h[2c] + i*h[2c+1]; raw Z (all 128 bins) to d_z.
__global__ void k_rfft_y() {
    extern __shared__ float4 sm4[];
    float4* bufA = sm4;                 // 128*6
    float4* bufB = sm4 + 128*6;
    __shared__ float2 tw[128];
    int tid = threadIdx.x;
    if (tid < 128) tw[tid] = d_tw[tid];
    __syncthreads();
    int row = blockIdx.x;
    const float4* hsrc4 = (const float4*)(d_h + (size_t)row * YY * WW);
    float4* zo = (float4*)(d_z + (size_t)row * 128 * 12);
    auto ld = [&](int p, int lp) { return hsrc4[p*6 + lp]; };
    auto st = [&](int p, int lp, float4 v) { zo[p*6 + lp] = v; };
    fft128_io<6,false,512>(bufA, bufB, tid, tw, ld, st);
}

// ---------------- fused fft-x + spectral matmul + ifft-x ----------------------
// block = (yh, batch-pair of 2). 48 lines = 24 float4 lanes. smem 96KB, 2 CTA/SM
// Preload reconstructs hf from raw packed Z: A=(Zk+conj(Zm))/2, B=(Zk-conj(Zm))/2i.
__global__ __launch_bounds__(512) void k_spectral(int layer) {
    extern __shared__ float4 sm4[];
    float4* bufA = sm4;                 // 128*24
    float4* bufB = sm4 + 128*24;
    __shared__ float2 tw[128];
    int tid = threadIdx.x;
    if (tid < 128) tw[tid] = d_tw[tid];
    int yh  = blockIdx.x >> 2;
    int b0i = (blockIdx.x & 3) * 2;

    // streaming preload + unscramble: Z[yh], Z[128-yh] -> hf pairs -> bufA
    {
        int ym = (128 - yh) & 127;
        #pragma unroll
        for (int k = 0; k < 6; k++) {
            int idx = tid + k*512;
            int x = idx / 24, l = idx % 24;
            int b = b0i + l/12, ip = l % 12;
            const float2* zr = d_z + (size_t)(b*XX + x) * 128 * 12;
            float2 Zk = zr[yh*12 + ip];
            float2 Zm = zr[ym*12 + ip];
            bufA[idx] = make_float4(0.5f*(Zk.x + Zm.x), 0.5f*(Zk.y - Zm.y),
                                    0.5f*(Zk.y + Zm.y), 0.5f*(Zm.x - Zk.x));
        }
    }
    __syncthreads();

    // forward x-FFT: bufA -> F in bufB
    auto ldf = [&](int p, int lp) { return bufA[p*24 + lp]; };
    auto stf = [&](int p, int lp, float4 v) { bufB[p*24 + lp] = v; };
    fft128_io<24,false,512>(bufB, bufA, tid, tw, ldf, stf);
    __syncthreads();

    // yf[b][o] = sum_i hf[b][i] * w[i][o]; F=bufB -> G=bufA
    const float2* wt = d_wt + (size_t)layer * NFREQ * IOSZ;
    const float2* F = (const float2*)bufB;
    float4* G4 = bufA;
    #pragma unroll 2
    for (int j = tid; j < 128*12; j += 512) {
        int x = j / 12, op = j % 12, o = op * 2;
        const float4* wp4 = (const float4*)(wt + ((size_t)x*YHH + yh)*IOSZ + o);
        const float2* hp  = F + x*48;
        float2 a00 = {0,0}, a01 = {0,0}, a10 = {0,0}, a11 = {0,0};
        #pragma unroll
        for (int i = 0; i < WW; i++) {
            float4 w4 = __ldg(wp4 + i*12);
            float2 w0 = make_float2(w4.x, w4.y);
            float2 w1 = make_float2(w4.z, w4.w);
            float2 h0 = hp[i], h1 = hp[24+i];
            a00.x += h0.x*w0.x - h0.y*w0.y;  a00.y += h0.x*w0.y + h0.y*w0.x;
            a01.x += h0.x*w1.x - h0.y*w1.y;  a01.y += h0.x*w1.y + h0.y*w1.x;
            a10.x += h1.x*w0.x - h1.y*w0.y;  a10.y += h1.x*w0.y + h1.y*w0.x;
            a11.x += h1.x*w1.x - h1.y*w1.y;  a11.y += h1.x*w1.y + h1.y*w1.x;
        }
        G4[(x*48 + o) >> 1]      = make_float4(a00.x, a00.y, a01.x, a01.y);
        G4[(x*48 + 24 + o) >> 1] = make_float4(a10.x, a10.y, a11.x, a11.y);
    }
    __syncthreads();

    // inverse x-FFT: G=bufA -> scatter to d_spec
    float4* sp4 = (float4*)d_spec;
    auto ldi = [&](int p, int lp) { return bufA[p*24 + lp]; };
    auto sti = [&](int p, int lp, float4 v) {
        int b = b0i + lp/12, ip = lp % 12;
        sp4[(((size_t)b*XX + p)*YHH + yh)*12 + ip] = v;
    };
    fft128_io<24,true,512>(bufB, bufA, tid, tw, ldi, sti);
}

// ---------------- fused irfft-y + 1x1 conv + relu (+ out-map) (+ next rfft-y) -
// ONE row per block, 512 threads, 36.8KB smem -> 4 CTA/SM.
// Forward y-FFT stores raw Z directly to d_z (unscramble moved to k_spectral).
__global__ __launch_bounds__(512) void k_update(int layer, int t, int Trt, int flags,
                         const float* __restrict__ conv_w,
                         const float* __restrict__ conv_b,
                         const float* __restrict__ out_w,
                         const float* __restrict__ out_b,
                         float* __restrict__ outp) {
    extern __shared__ float4 sm4[];
    float4* A4  = sm4;                        // 128*6 float4 = 12 complex lines
    float4* B4  = sm4 + 128*6;
    float*  hrow = (float*)(sm4 + 2*128*6);   // 128*24 floats
    __shared__ float2 tw[128];
    int tid = threadIdx.x;
    if (tid < 128) tw[tid] = d_tw[tid];
    int row = blockIdx.x;                 // b*128 + x

    // load previous h (for 1x1 conv) — independent stream, issue first
    {
        const float4* hsrc4 = (const float4*)(d_h + (size_t)row * YY * WW);
        float4* hrow4 = (float4*)hrow;
        for (int i = tid; i < YY*WW/4; i += 512) hrow4[i] = hsrc4[i];
    }

    // streaming pack: Zp[k] = A + iB (Hermitian fold, DC/Nyq imag drop) -> A4
    {
        const float4* sp = (const float4*)(d_spec + (size_t)row * YHH * WW);
        for (int idx = tid; idx < 128*6; idx += 512) {
            int k = idx / 6, cp = idx % 6;
            float2 z0, z1;
            if (k == 0 || k == 64) {
                float4 v0 = sp[k*12 + 2*cp], v1 = sp[k*12 + 2*cp + 1];
                z0 = make_float2(v0.x, v0.z);
                z1 = make_float2(v1.x, v1.z);
            } else if (k < 64) {
                float4 v0 = sp[k*12 + 2*cp], v1 = sp[k*12 + 2*cp + 1];
                z0 = make_float2(v0.x - v0.w, v0.y + v0.z);
                z1 = make_float2(v1.x - v1.w, v1.y + v1.z);
            } else {
                float4 v0 = sp[(128-k)*12 + 2*cp], v1 = sp[(128-k)*12 + 2*cp + 1];
                z0 = make_float2(v0.x + v0.w, v0.z - v0.y);
                z1 = make_float2(v1.x + v1.w, v1.z - v1.y);
            }
            A4[idx] = make_float4(z0.x, z0.y, z1.x, z1.y);
        }
    }
    __syncthreads();   // tw + hrow + packed A4 all visible

    // inverse y-FFT: A4 -> R in B4
    auto ldz = [&](int p, int lp) { return A4[p*6 + lp]; };
    auto stR = [&](int p, int lp, float4 v) { B4[p*6 + lp] = v; };
    fft128_io<6,true,512>(B4, A4, tid, tw, ldz, stR);
    __syncthreads();

    // conv + relu; R=B4 -> packed h_new pairs P=A4 and global d_h
    const float* cw = conv_w + layer * IOSZ;
    const float* cb = conv_b + layer * WW;
    const float2* R2 = (const float2*)B4;     // [y*12 + c]
    float2* P2 = (float2*)A4;
    float2* hdst2 = (float2*)(d_h + (size_t)row * YY * WW);
    #pragma unroll 2
    for (int idx = tid; idx < 128*12; idx += 512) {
        int y = idx / 12, c = idx % 12, o = 2*c;
        float2 z = R2[idx];
        float acc0 = cb[o], acc1 = cb[o+1];
        const float* hr = hrow + y*WW;
        #pragma unroll
        for (int i = 0; i < WW; i++) {
            float hv = hr[i];
            float2 w = __ldg((const float2*)(cw + i*WW + o));
            acc0 += hv * w.x;
            acc1 += hv * w.y;
        }
        float hn0 = fmaxf(z.x * (1.0f/16384.0f), 0.0f) + acc0;
        float hn1 = fmaxf(z.y * (1.0f/16384.0f), 0.0f) + acc1;
        P2[idx] = make_float2(hn0, hn1);
        hdst2[y*12 + c] = make_float2(hn0, hn1);
    }
    __syncthreads();

    if (flags & 1) {   // out mapping (COUT = 1); reads P=A4 (safe: fwd FFT's
        int b = row >> 7, xs = row & 127;     // first A4 write is stage 2,
        float ob0 = out_b[0];                 // behind the stage-1 barrier)
        for (int y = tid; y < YY; y += 512) {
            float s = ob0;
            #pragma unroll
            for (int c = 0; c < 12; c++) {
                float2 z = P2[y*12 + c];
                s += z.x * __ldg(out_w + 2*c) + z.y * __ldg(out_w + 2*c + 1);
            }
            outp[(((size_t)b*Trt + t)*XX + xs)*YY + y] = s;
        }
    }

    if (flags & 2) {   // forward rfft-y of P=A4 -> raw Z straight to global
        float4* zo = (float4*)(d_z + (size_t)row * 128 * 12);
        auto ldP = [&](int p, int lp) { return A4[p*6 + lp]; };
        auto stZ = [&](int p, int lp, float4 v) { zo[p*6 + lp] = v; };
        fft128_io<6,false,512>(B4, A4, tid, tw, ldP, stZ);
    }
}

// ---------------- host launcher ----------------------------------------------
extern "C" void kernel_launch(void* const* d_in, const int* in_sizes, int n_in,
                              void* d_out, int out_size) {
    const float* x      = (const float*)d_in[0];
    const float* in_w   = (const float*)d_in[1];
    const float* in_b   = (const float*)d_in[2];
    const float* spec_w = (const float*)d_in[3];
    const float* conv_w = (const float*)d_in[4];
    const float* conv_b = (const float*)d_in[5];
    const float* out_w  = (const float*)d_in[6];
    const float* out_b  = (const float*)d_in[7];
    float* outp = (float*)d_out;
    int Trt = out_size / (BB * XX * YY);

    const int SMEM_ROW  = 2 * 128 * 6 * (int)sizeof(float4);      // 24576
    const int SMEM_SPEC = 2 * 128 * 24 * (int)sizeof(float4);     // 98304
    const int SMEM_UPD  = 2 * 128 * 6 * (int)sizeof(float4)
                        + 128 * WW * (int)sizeof(float);          // 36864
    cudaFuncSetAttribute(k_spectral, cudaFuncAttributeMaxDynamicSharedMemorySize, SMEM_SPEC);
    cudaFuncSetAttribute(k_rfft_y,   cudaFuncAttributeMaxDynamicSharedMemorySize, SMEM_ROW);
    cudaFuncSetAttribute(k_update,   cudaFuncAttributeMaxDynamicSharedMemorySize, SMEM_UPD);

    k_twiddle<<<1, 128>>>();

    dim3 tb(32, 8), tg(NFREQ/32, IOSZ/32, DD);
    k_transpose<<<tg, tb>>>((const float2*)spec_w);

    k_inmap<<<(NPIX + 255)/256, 256>>>(x, in_w, in_b);
    k_rfft_y<<<NROWS, 512, SMEM_ROW>>>();

    for (int t = 0; t < Trt; t++) {
        for (int d = 0; d < DD; d++) {
            k_spectral<<<4*YHH, 512, SMEM_SPEC>>>(d);
            int flags = (d == DD-1 ? 1 : 0)
                      | ((t == Trt-1 && d == DD-1) ? 0 : 2);
            k_update<<<NROWS, 512, SMEM_UPD>>>(d, t, Trt, flags,
                                               conv_w, conv_b, out_w, out_b, outp);
        }
    }
}